// round 3
// baseline (speedup 1.0000x reference)
#include <cuda_runtime.h>
#include <cuda_bf16.h>
#include <cstdint>

#define NPTS 8192
#define DIM  512
#define MARGINF 0.3f

#define BM 128
#define BN 128
#define BKB 128                  // fp8 elems (=bytes) per K chunk
#define NCHUNK (DIM/BKB)         // 4
#define GB (NPTS/BM)             // 64 tile-blocks per side
#define NPART (GB*(GB+1)/2)      // 2080 upper-triangular tiles

#define STAGES 3
#define STAGE_BYTES 32768        // 16KB A + 16KB B
#define SMEM_BYTES (1024 + STAGES*STAGE_BYTES)

// ---------------- device scratch (no allocations allowed) ----------------
__device__ uint8_t g_X[NPTS*DIM];   // 4 MB e4m3 copy of inputs
__device__ int   g_lab[NPTS];
__device__ float g_part[NPART];

// ---------------- helpers ----------------
__device__ __forceinline__ uint32_t smem_u32(const void* p){
    uint32_t a;
    asm("{ .reg .u64 t; cvta.to.shared.u64 t, %1; cvt.u32.u64 %0, t; }"
        : "=r"(a) : "l"(p));
    return a;
}
#define SW128(o) ((o) ^ (((o) >> 3) & 0x70))

__device__ __forceinline__ void cp16(uint32_t s, const void* g){
    asm volatile("cp.async.cg.shared.global [%0], [%1], 16;" :: "r"(s), "l"(g));
}
#define CP_COMMIT() asm volatile("cp.async.commit_group;" ::: "memory")
#define CP_WAIT(n)  asm volatile("cp.async.wait_group %0;" :: "n"(n) : "memory")

__device__ __forceinline__ void ldm_x4(uint32_t* r, uint32_t addr){
    asm volatile("ldmatrix.sync.aligned.m8n8.x4.shared.b16 {%0,%1,%2,%3}, [%4];"
                 : "=r"(r[0]), "=r"(r[1]), "=r"(r[2]), "=r"(r[3]) : "r"(addr));
}
// m16n8k32 e4m3 QMMA, fp32 accum
__device__ __forceinline__ void mma_fp8(float* d, const uint32_t* a,
                                        uint32_t b0, uint32_t b1){
    asm volatile(
        "mma.sync.aligned.m16n8k32.row.col.f32.e4m3.e4m3.f32 "
        "{%0,%1,%2,%3}, {%4,%5,%6,%7}, {%8,%9}, {%0,%1,%2,%3};"
        : "+f"(d[0]), "+f"(d[1]), "+f"(d[2]), "+f"(d[3])
        : "r"(a[0]), "r"(a[1]), "r"(a[2]), "r"(a[3]), "r"(b0), "r"(b1));
}
// pack 4 floats -> 4 e4m3 bytes (byte0 = f0)
__device__ __forceinline__ uint32_t pack_e4m3x4(float f0, float f1, float f2, float f3){
    uint32_t out;
    asm("{ .reg .b16 lo, hi;\n"
        "  cvt.rn.satfinite.e4m3x2.f32 lo, %2, %1;\n"
        "  cvt.rn.satfinite.e4m3x2.f32 hi, %4, %3;\n"
        "  mov.b32 %0, {lo, hi}; }"
        : "=r"(out) : "f"(f0), "f"(f1), "f"(f2), "f"(f3));
    return out;
}

// ---------------- kernel 1: convert inputs to e4m3 + normalize labels ----------------
__global__ void prep_kernel(const float* __restrict__ x, const void* __restrict__ tgt){
    const int idx = blockIdx.x * blockDim.x + threadIdx.x;   // NPTS*DIM/4 threads
    const float4 v = ((const float4*)x)[idx];
    ((uint32_t*)g_X)[idx] = pack_e4m3x4(v.x, v.y, v.z, v.w);

    if (blockIdx.x == 0){
        // detect int64 vs int32 labels: values in [0,128); if int64, all odd words are 0
        const int* w = (const int*)tgt;
        bool is64 = true;
        #pragma unroll 1
        for (int k = 0; k < 64; k++)
            if (w[2*k + 1] != 0) { is64 = false; break; }
        if (is64){
            const long long* t64 = (const long long*)tgt;
            for (int i = threadIdx.x; i < NPTS; i += blockDim.x)
                g_lab[i] = (int)t64[i];
        } else {
            for (int i = threadIdx.x; i < NPTS; i += blockDim.x)
                g_lab[i] = w[i];
        }
    }
}

// ---------------- kernel 2: FP8 QMMA GEMM (upper-tri tiles) + fused masked loss ----------------
__global__ void __launch_bounds__(256, 2) contrastive_gemm(){
    extern __shared__ char smem[];
    const uint32_t sb = smem_u32(smem);
    const int tid = threadIdx.x;
    const int wid = tid >> 5, lane = tid & 31;

    // map blockIdx.x -> upper-triangular (bi, bj), bi <= bj
    int bi = 0, rem = blockIdx.x;
    while (rem >= GB - bi){ rem -= GB - bi; bi++; }
    const int bj = bi + rem;
    const int i0 = bi * BM, j0 = bj * BN;
    const bool diag = (bi == bj);

    // labels into smem
    int* ilab = (int*)smem;            // 128 ints
    int* jlab = ilab + 128;            // 128 ints
    if (tid < 128)        ilab[tid]       = g_lab[i0 + tid];
    else                  jlab[tid - 128] = g_lab[j0 + (tid - 128)];

    // cp.async tile loader: thread -> (row r + {0,32,64,96}, 16B chunk v)
    const int rr = tid >> 3, vv = tid & 7;
    auto load_stage = [&](int c){
        const uint32_t sA = sb + 1024 + (c % STAGES) * STAGE_BYTES;
        const uint32_t sB = sA + 16384;
        const int kc = c * BKB;
        #pragma unroll
        for (int p = 0; p < 4; p++){
            const int r = rr + p * 32;
            cp16(sA + SW128(r * 128 + vv * 16),
                 g_X + (size_t)(i0 + r) * DIM + kc + vv * 16);
            cp16(sB + SW128(r * 128 + vv * 16),
                 g_X + (size_t)(j0 + r) * DIM + kc + vv * 16);
        }
    };

    load_stage(0); CP_COMMIT();
    load_stage(1); CP_COMMIT();

    const int wm0 = (wid & 3) * 32;     // warp row base   (4 warps in M)
    const int wn0 = (wid >> 2) * 64;    // warp col base   (2 warps in N)

    float acc[2][8][4];
    #pragma unroll
    for (int tm = 0; tm < 2; tm++)
        #pragma unroll
        for (int tn = 0; tn < 8; tn++)
            #pragma unroll
            for (int e = 0; e < 4; e++) acc[tm][tn][e] = 0.f;

    const int lrow = lane & 15, lhi = lane >> 4;

    for (int c = 0; c < NCHUNK; c++){
        CP_WAIT(1);
        __syncthreads();
        if (c + 2 < NCHUNK) load_stage(c + 2);
        CP_COMMIT();

        const uint32_t sA = sb + 1024 + (c % STAGES) * STAGE_BYTES;
        const uint32_t sB = sA + 16384;
        #pragma unroll
        for (int ks = 0; ks < 4; ks++){
            const int cb = ks * 32 + lhi * 16;     // 32 B = k32 fp8 per mma
            uint32_t a[2][4];
            #pragma unroll
            for (int tm = 0; tm < 2; tm++)
                ldm_x4(a[tm], sA + SW128((wm0 + tm * 16 + lrow) * 128 + cb));
            uint32_t b[4][4];
            #pragma unroll
            for (int tp = 0; tp < 4; tp++)
                ldm_x4(b[tp], sB + SW128((wn0 + tp * 16 + lrow) * 128 + cb));
            #pragma unroll
            for (int tm = 0; tm < 2; tm++)
                #pragma unroll
                for (int tp = 0; tp < 4; tp++){
                    mma_fp8(acc[tm][2*tp],     a[tm], b[tp][0], b[tp][2]);
                    mma_fp8(acc[tm][2*tp + 1], a[tm], b[tp][1], b[tp][3]);
                }
        }
        __syncthreads();
    }

    // ---------------- fused masked loss on register accumulators ----------------
    const int r0 = lane >> 2, c0 = (lane & 3) * 2;
    float loss = 0.f;
    #pragma unroll
    for (int tm = 0; tm < 2; tm++){
        const int rowA = wm0 + tm * 16 + r0;
        const int liA  = ilab[rowA];
        const int liB  = ilab[rowA + 8];
        #pragma unroll
        for (int tn = 0; tn < 8; tn++){
            const int colb = wn0 + tn * 8 + c0;
            const int lj0 = jlab[colb], lj1 = jlab[colb + 1];
            #pragma unroll
            for (int e = 0; e < 4; e++){
                const float v = acc[tm][tn][e];
                const int row = (e >> 1) ? rowA + 8 : rowA;
                const int li  = (e >> 1) ? liB : liA;
                const int lj  = (e & 1) ? lj1 : lj0;
                float w = 2.f;
                if (diag){
                    const int gi = row, gj = colb + (e & 1);
                    w = (gi < gj) ? 2.f : ((gi == gj) ? 1.f : 0.f);
                }
                float l;
                if (li == lj) l = (v < 1.f) ? (1.f - v) : 0.f;
                else          l = (v > MARGINF) ? v : 0.f;
                loss += w * l;
            }
        }
    }

    // block reduction -> per-tile partial
    #pragma unroll
    for (int o = 16; o; o >>= 1) loss += __shfl_xor_sync(0xffffffffu, loss, o);
    __syncthreads();                      // labels no longer needed
    float* wsum = (float*)smem;
    if (lane == 0) wsum[wid] = loss;
    __syncthreads();
    if (tid == 0){
        float s = 0.f;
        #pragma unroll
        for (int w = 0; w < 8; w++) s += wsum[w];
        g_part[blockIdx.x] = s;
    }
}

// ---------------- kernel 3: deterministic final reduction ----------------
__global__ void reduce_kernel(float* __restrict__ out){
    __shared__ float sm[512];
    const int t = threadIdx.x;
    float v = 0.f;
    for (int i = t; i < NPART; i += 512) v += g_part[i];
    sm[t] = v;
    __syncthreads();
    for (int s = 256; s > 0; s >>= 1){
        if (t < s) sm[t] += sm[t + s];
        __syncthreads();
    }
    if (t == 0) out[0] = sm[0] / (float)NPTS;
}

// ---------------- launch ----------------
extern "C" void kernel_launch(void* const* d_in, const int* in_sizes, int n_in,
                              void* d_out, int out_size){
    const float* x   = (const float*)d_in[0];
    const void*  tgt = d_in[1];
    float* out = (float*)d_out;

    cudaFuncSetAttribute(contrastive_gemm,
                         cudaFuncAttributeMaxDynamicSharedMemorySize, SMEM_BYTES);

    prep_kernel<<<NPTS*DIM/1024, 256>>>(x, tgt);
    contrastive_gemm<<<NPART, 256, SMEM_BYTES>>>();
    reduce_kernel<<<1, 512>>>(out);
}

// round 4
// speedup vs baseline: 1.0955x; 1.0955x over previous
#include <cuda_runtime.h>
#include <cuda_bf16.h>
#include <cstdint>

#define NPTS 8192
#define DIM  512
#define MARGINF 0.3f

#define BM 128
#define BN 256
#define BK 64                    // bf16 elems per K chunk (128 B per row)
#define NCHUNK (DIM/BK)          // 8
#define GBI (NPTS/BM)            // 64 row blocks
#define GBJ (NPTS/BN)            // 32 col blocks
#define NPART 1056               // sum_{bj=0..31} (2*bj+2)

#define STAGES 4
#define STAGE_BYTES 49152        // 16KB A (128 rows) + 32KB B (256 rows)
#define SMEM_BYTES (2048 + STAGES*STAGE_BYTES)

// ---------------- device scratch (no allocations allowed) ----------------
__device__ __nv_bfloat16 g_X[NPTS*DIM];   // 8 MB bf16 copy of inputs
__device__ int   g_lab[NPTS];
__device__ float g_part[NPART];

// ---------------- helpers ----------------
__device__ __forceinline__ uint32_t smem_u32(const void* p){
    uint32_t a;
    asm("{ .reg .u64 t; cvta.to.shared.u64 t, %1; cvt.u32.u64 %0, t; }"
        : "=r"(a) : "l"(p));
    return a;
}
#define SW128(o) ((o) ^ (((o) >> 3) & 0x70))

__device__ __forceinline__ void cp16(uint32_t s, const void* g){
    asm volatile("cp.async.cg.shared.global [%0], [%1], 16;" :: "r"(s), "l"(g));
}
#define CP_COMMIT() asm volatile("cp.async.commit_group;" ::: "memory")
#define CP_WAIT(n)  asm volatile("cp.async.wait_group %0;" :: "n"(n) : "memory")

__device__ __forceinline__ void ldm_x4(uint32_t* r, uint32_t addr){
    asm volatile("ldmatrix.sync.aligned.m8n8.x4.shared.b16 {%0,%1,%2,%3}, [%4];"
                 : "=r"(r[0]), "=r"(r[1]), "=r"(r[2]), "=r"(r[3]) : "r"(addr));
}
__device__ __forceinline__ void mma16816(float* d, const uint32_t* a,
                                         uint32_t b0, uint32_t b1){
    asm volatile(
        "mma.sync.aligned.m16n8k16.row.col.f32.bf16.bf16.f32 "
        "{%0,%1,%2,%3}, {%4,%5,%6,%7}, {%8,%9}, {%0,%1,%2,%3};"
        : "+f"(d[0]), "+f"(d[1]), "+f"(d[2]), "+f"(d[3])
        : "r"(a[0]), "r"(a[1]), "r"(a[2]), "r"(a[3]), "r"(b0), "r"(b1));
}

// ---------------- kernel 1: convert inputs to bf16 + normalize labels ----------------
__global__ void prep_kernel(const float* __restrict__ x, const void* __restrict__ tgt){
    const int idx = blockIdx.x * blockDim.x + threadIdx.x;   // NPTS*DIM/4 threads
    const float4 v = ((const float4*)x)[idx];
    __nv_bfloat162 p0 = __float22bfloat162_rn(make_float2(v.x, v.y));
    __nv_bfloat162 p1 = __float22bfloat162_rn(make_float2(v.z, v.w));
    uint2 st;
    st.x = *(uint32_t*)&p0;
    st.y = *(uint32_t*)&p1;
    ((uint2*)g_X)[idx] = st;

    if (blockIdx.x == 0){
        // detect int64 vs int32 labels: values in [0,128); if int64, all odd words are 0
        const int* w = (const int*)tgt;
        bool is64 = true;
        #pragma unroll 1
        for (int k = 0; k < 64; k++)
            if (w[2*k + 1] != 0) { is64 = false; break; }
        if (is64){
            const long long* t64 = (const long long*)tgt;
            for (int i = threadIdx.x; i < NPTS; i += blockDim.x)
                g_lab[i] = (int)t64[i];
        } else {
            for (int i = threadIdx.x; i < NPTS; i += blockDim.x)
                g_lab[i] = w[i];
        }
    }
}

// ---------------- kernel 2: bf16 HMMA 128x256 tiles + fused masked loss ----------------
__global__ void __launch_bounds__(256, 1) contrastive_gemm(){
    extern __shared__ char smem[];
    const uint32_t sb = smem_u32(smem);
    const int tid = threadIdx.x;
    const int wid = tid >> 5, lane = tid & 31;

    // map blockIdx.x -> (bi, bj): tiles with any upper-triangle overlap (bi <= 2*bj+1)
    int bj = 0, rem = blockIdx.x;
    while (rem >= 2 * bj + 2){ rem -= 2 * bj + 2; bj++; }
    const int bi = rem;
    const int i0 = bi * BM, j0 = bj * BN;
    const bool alltwo = (i0 + BM <= j0);    // tile entirely above diagonal

    // labels into smem: ilab[128] @0, jlab[256] @512
    int* ilab = (int*)smem;
    int* jlab = (int*)(smem + 512);
    if (tid < 128) ilab[tid] = g_lab[i0 + tid];
    jlab[tid] = g_lab[j0 + tid];

    // cp.async tile loader: 256 threads, 384 rows x 128B per stage
    const int rr = tid >> 3, vv = tid & 7;   // 8 threads per 128B row
    auto load_stage = [&](int c){
        const uint32_t sA = sb + 2048 + (c & (STAGES - 1)) * STAGE_BYTES;
        const uint32_t sB = sA + 16384;
        const int kc = c * BK;
        #pragma unroll
        for (int p = 0; p < 4; p++){
            const int r = rr + p * 32;
            cp16(sA + SW128(r * 128 + vv * 16),
                 g_X + (size_t)(i0 + r) * DIM + kc + vv * 8);
        }
        #pragma unroll
        for (int p = 0; p < 8; p++){
            const int r = rr + p * 32;
            cp16(sB + SW128(r * 128 + vv * 16),
                 g_X + (size_t)(j0 + r) * DIM + kc + vv * 8);
        }
    };

    load_stage(0); CP_COMMIT();
    load_stage(1); CP_COMMIT();
    load_stage(2); CP_COMMIT();

    const int wm0 = (wid & 1) * 64;     // 2 warps in M
    const int wn0 = (wid >> 1) * 64;    // 4 warps in N

    float acc[4][8][4];                 // warp tile 64x64 -> 128 floats/thread
    #pragma unroll
    for (int tm = 0; tm < 4; tm++)
        #pragma unroll
        for (int tn = 0; tn < 8; tn++)
            #pragma unroll
            for (int e = 0; e < 4; e++) acc[tm][tn][e] = 0.f;

    const int lrow = lane & 15, lhi = lane >> 4;

    for (int c = 0; c < NCHUNK; c++){
        CP_WAIT(2);
        __syncthreads();
        if (c + 3 < NCHUNK) load_stage(c + 3);
        CP_COMMIT();

        const uint32_t sA = sb + 2048 + (c & (STAGES - 1)) * STAGE_BYTES;
        const uint32_t sB = sA + 16384;
        #pragma unroll
        for (int ks = 0; ks < 4; ks++){
            const int cb = ks * 32 + lhi * 16;
            uint32_t a[4][4];
            #pragma unroll
            for (int tm = 0; tm < 4; tm++)
                ldm_x4(a[tm], sA + SW128((wm0 + tm * 16 + lrow) * 128 + cb));
            uint32_t b[4][4];
            #pragma unroll
            for (int tp = 0; tp < 4; tp++)
                ldm_x4(b[tp], sB + SW128((wn0 + tp * 16 + lrow) * 128 + cb));
            #pragma unroll
            for (int tm = 0; tm < 4; tm++)
                #pragma unroll
                for (int tp = 0; tp < 4; tp++){
                    mma16816(acc[tm][2*tp],     a[tm], b[tp][0], b[tp][2]);
                    mma16816(acc[tm][2*tp + 1], a[tm], b[tp][1], b[tp][3]);
                }
        }
        __syncthreads();
    }

    // ---------------- fused masked loss on register accumulators ----------------
    const int r0 = lane >> 2, c0 = (lane & 3) * 2;
    float loss = 0.f;
    #pragma unroll
    for (int tm = 0; tm < 4; tm++){
        const int rowA = wm0 + tm * 16 + r0;
        const int liA  = ilab[rowA];
        const int liB  = ilab[rowA + 8];
        #pragma unroll
        for (int tn = 0; tn < 8; tn++){
            const int colb = wn0 + tn * 8 + c0;
            const int lj0 = jlab[colb], lj1 = jlab[colb + 1];
            #pragma unroll
            for (int e = 0; e < 4; e++){
                const float v = acc[tm][tn][e];
                const int row = (e >> 1) ? rowA + 8 : rowA;
                const int li  = (e >> 1) ? liB : liA;
                const int lj  = (e & 1) ? lj1 : lj0;
                float w = 2.f;
                if (!alltwo){
                    const int gi = i0 + row, gj = j0 + colb + (e & 1);
                    w = (gi < gj) ? 2.f : ((gi == gj) ? 1.f : 0.f);
                }
                float l;
                if (li == lj) l = (v < 1.f) ? (1.f - v) : 0.f;
                else          l = (v > MARGINF) ? v : 0.f;
                loss += w * l;
            }
        }
    }

    // block reduction -> per-tile partial
    #pragma unroll
    for (int o = 16; o; o >>= 1) loss += __shfl_xor_sync(0xffffffffu, loss, o);
    float* wsum = (float*)(smem + 1536);
    if (lane == 0) wsum[wid] = loss;
    __syncthreads();
    if (tid == 0){
        float s = 0.f;
        #pragma unroll
        for (int w = 0; w < 8; w++) s += wsum[w];
        g_part[blockIdx.x] = s;
    }
}

// ---------------- kernel 3: deterministic final reduction ----------------
__global__ void reduce_kernel(float* __restrict__ out){
    __shared__ float sm[512];
    const int t = threadIdx.x;
    float v = 0.f;
    for (int i = t; i < NPART; i += 512) v += g_part[i];
    sm[t] = v;
    __syncthreads();
    for (int s = 256; s > 0; s >>= 1){
        if (t < s) sm[t] += sm[t + s];
        __syncthreads();
    }
    if (t == 0) out[0] = sm[0] / (float)NPTS;
}

// ---------------- launch ----------------
extern "C" void kernel_launch(void* const* d_in, const int* in_sizes, int n_in,
                              void* d_out, int out_size){
    const float* x   = (const float*)d_in[0];
    const void*  tgt = d_in[1];
    float* out = (float*)d_out;

    cudaFuncSetAttribute(contrastive_gemm,
                         cudaFuncAttributeMaxDynamicSharedMemorySize, SMEM_BYTES);

    prep_kernel<<<NPTS*DIM/1024, 256>>>(x, tgt);
    contrastive_gemm<<<NPART, 256, SMEM_BYTES>>>();
    reduce_kernel<<<1, 512>>>(out);
}

// round 5
// speedup vs baseline: 1.1020x; 1.0059x over previous
#include <cuda_runtime.h>
#include <cuda_bf16.h>
#include <cstdint>

#define NPTS 8192
#define DIM  512
#define MARGINF 0.3f

#define BM 128
#define BN 256
#define BK 64                    // bf16 elems per K chunk (128 B per row)
#define NCHUNK (DIM/BK)          // 8
#define NPART 1056               // tiles with upper-triangle overlap

#define STAGES 3
#define STAGE_BYTES 49152        // 16KB A (128 rows) + 32KB B (256 rows)
#define SMEM_BYTES (2048 + STAGES*STAGE_BYTES)

// ---------------- device scratch (no allocations allowed) ----------------
__device__ __nv_bfloat16 g_X[NPTS*DIM];   // 8 MB bf16 copy of inputs
__device__ int   g_lab[NPTS];
__device__ float g_part[NPART];

// ---------------- helpers ----------------
__device__ __forceinline__ uint32_t smem_u32(const void* p){
    uint32_t a;
    asm("{ .reg .u64 t; cvta.to.shared.u64 t, %1; cvt.u32.u64 %0, t; }"
        : "=r"(a) : "l"(p));
    return a;
}
#define SW128(o) ((o) ^ (((o) >> 3) & 0x70))

__device__ __forceinline__ void cp16(uint32_t s, const void* g){
    asm volatile("cp.async.cg.shared.global [%0], [%1], 16;" :: "r"(s), "l"(g));
}
#define CP_COMMIT() asm volatile("cp.async.commit_group;" ::: "memory")
#define CP_WAIT(n)  asm volatile("cp.async.wait_group %0;" :: "n"(n) : "memory")

__device__ __forceinline__ void ldm_x4(uint32_t* r, uint32_t addr){
    asm volatile("ldmatrix.sync.aligned.m8n8.x4.shared.b16 {%0,%1,%2,%3}, [%4];"
                 : "=r"(r[0]), "=r"(r[1]), "=r"(r[2]), "=r"(r[3]) : "r"(addr));
}
__device__ __forceinline__ void mma16816(float* d, const uint32_t* a,
                                         uint32_t b0, uint32_t b1){
    asm volatile(
        "mma.sync.aligned.m16n8k16.row.col.f32.bf16.bf16.f32 "
        "{%0,%1,%2,%3}, {%4,%5,%6,%7}, {%8,%9}, {%0,%1,%2,%3};"
        : "+f"(d[0]), "+f"(d[1]), "+f"(d[2]), "+f"(d[3])
        : "r"(a[0]), "r"(a[1]), "r"(a[2]), "r"(a[3]), "r"(b0), "r"(b1));
}

// ---------------- kernel 1: convert inputs to bf16 + normalize labels ----------------
// 1024 blocks x 256 threads, each thread converts 4 coalesced float4s (MLP=4)
__global__ void prep_kernel(const float* __restrict__ x, const void* __restrict__ tgt){
    const int base = blockIdx.x * 1024 + threadIdx.x;
    float4 v[4];
    #pragma unroll
    for (int u = 0; u < 4; u++) v[u] = ((const float4*)x)[base + u * 256];
    #pragma unroll
    for (int u = 0; u < 4; u++){
        __nv_bfloat162 p0 = __float22bfloat162_rn(make_float2(v[u].x, v[u].y));
        __nv_bfloat162 p1 = __float22bfloat162_rn(make_float2(v[u].z, v[u].w));
        uint2 st;
        st.x = *(uint32_t*)&p0;
        st.y = *(uint32_t*)&p1;
        ((uint2*)g_X)[base + u * 256] = st;
    }

    if (blockIdx.x == 0){
        // detect int64 vs int32 labels: values in [0,128); if int64, all odd words are 0
        const int* w = (const int*)tgt;
        bool is64 = true;
        #pragma unroll 1
        for (int k = 0; k < 64; k++)
            if (w[2*k + 1] != 0) { is64 = false; break; }
        if (is64){
            const long long* t64 = (const long long*)tgt;
            for (int i = threadIdx.x; i < NPTS; i += blockDim.x)
                g_lab[i] = (int)t64[i];
        } else {
            for (int i = threadIdx.x; i < NPTS; i += blockDim.x)
                g_lab[i] = w[i];
        }
    }
}

// ---------------- kernel 2: bf16 HMMA 128x256 tile, 512 thr, fused loss ----------------
__global__ void __launch_bounds__(512, 1) contrastive_gemm(){
    extern __shared__ char smem[];
    const uint32_t sb = smem_u32(smem);
    const int tid = threadIdx.x;
    const int wid = tid >> 5, lane = tid & 31;

    // map blockIdx.x -> (bi, bj): tiles with upper-triangle overlap (bi <= 2*bj+1)
    int bj = 0, rem = blockIdx.x;
    while (rem >= 2 * bj + 2){ rem -= 2 * bj + 2; bj++; }
    const int bi = rem;
    const int i0 = bi * BM, j0 = bj * BN;
    const bool alltwo = (i0 + BM <= j0);    // tile entirely above diagonal

    // labels into smem: ilab[128] @0, jlab[256] @512
    int* ilab = (int*)smem;
    int* jlab = (int*)(smem + 512);
    if (tid < 128) ilab[tid] = g_lab[i0 + tid];
    if (tid < 256) jlab[tid] = g_lab[j0 + tid];

    // cp.async loader: 512 threads, 64 rows/pass, 8 threads x 16B per 128B row
    const int rr = tid >> 3, vv = tid & 7;
    auto load_stage = [&](int c){
        const uint32_t sA = sb + 2048 + (c % STAGES) * STAGE_BYTES;
        const uint32_t sB = sA + 16384;
        const int kc = c * BK;
        #pragma unroll
        for (int p = 0; p < 2; p++){
            const int r = rr + p * 64;
            cp16(sA + SW128(r * 128 + vv * 16),
                 g_X + (size_t)(i0 + r) * DIM + kc + vv * 8);
        }
        #pragma unroll
        for (int p = 0; p < 4; p++){
            const int r = rr + p * 64;
            cp16(sB + SW128(r * 128 + vv * 16),
                 g_X + (size_t)(j0 + r) * DIM + kc + vv * 8);
        }
    };

    load_stage(0); CP_COMMIT();
    load_stage(1); CP_COMMIT();

    const int wm0 = (wid & 3) * 32;     // 4 warps in M
    const int wn0 = (wid >> 2) * 64;    // 4 warps in N

    float acc[2][8][4];                 // warp tile 32x64
    #pragma unroll
    for (int tm = 0; tm < 2; tm++)
        #pragma unroll
        for (int tn = 0; tn < 8; tn++)
            #pragma unroll
            for (int e = 0; e < 4; e++) acc[tm][tn][e] = 0.f;

    const int lrow = lane & 15, lhi = lane >> 4;

    for (int c = 0; c < NCHUNK; c++){
        CP_WAIT(1);
        __syncthreads();                 // single barrier per chunk
        if (c + 2 < NCHUNK) load_stage(c + 2);
        CP_COMMIT();                     // empty commits keep group count aligned

        const uint32_t sA = sb + 2048 + (c % STAGES) * STAGE_BYTES;
        const uint32_t sB = sA + 16384;
        #pragma unroll
        for (int ks = 0; ks < 4; ks++){
            const int cb = ks * 32 + lhi * 16;
            uint32_t a[2][4];
            #pragma unroll
            for (int tm = 0; tm < 2; tm++)
                ldm_x4(a[tm], sA + SW128((wm0 + tm * 16 + lrow) * 128 + cb));
            uint32_t b[4][4];
            #pragma unroll
            for (int tp = 0; tp < 4; tp++)
                ldm_x4(b[tp], sB + SW128((wn0 + tp * 16 + lrow) * 128 + cb));
            #pragma unroll
            for (int tm = 0; tm < 2; tm++)
                #pragma unroll
                for (int tp = 0; tp < 4; tp++){
                    mma16816(acc[tm][2*tp],     a[tm], b[tp][0], b[tp][2]);
                    mma16816(acc[tm][2*tp + 1], a[tm], b[tp][1], b[tp][3]);
                }
        }
    }

    // ---------------- fused masked loss on register accumulators ----------------
    const int r0 = lane >> 2, c0 = (lane & 3) * 2;
    float loss = 0.f;
    #pragma unroll
    for (int tm = 0; tm < 2; tm++){
        const int rowA = wm0 + tm * 16 + r0;
        const int liA  = ilab[rowA];
        const int liB  = ilab[rowA + 8];
        #pragma unroll
        for (int tn = 0; tn < 8; tn++){
            const int colb = wn0 + tn * 8 + c0;
            const int lj0 = jlab[colb], lj1 = jlab[colb + 1];
            #pragma unroll
            for (int e = 0; e < 4; e++){
                const float v = acc[tm][tn][e];
                const int row = (e >> 1) ? rowA + 8 : rowA;
                const int li  = (e >> 1) ? liB : liA;
                const int lj  = (e & 1) ? lj1 : lj0;
                float w = 2.f;
                if (!alltwo){
                    const int gi = i0 + row, gj = j0 + colb + (e & 1);
                    w = (gi < gj) ? 2.f : ((gi == gj) ? 1.f : 0.f);
                }
                float l;
                if (li == lj) l = (v < 1.f) ? (1.f - v) : 0.f;
                else          l = (v > MARGINF) ? v : 0.f;
                loss += w * l;
            }
        }
    }

    // block reduction -> per-tile partial
    #pragma unroll
    for (int o = 16; o; o >>= 1) loss += __shfl_xor_sync(0xffffffffu, loss, o);
    float* wsum = (float*)(smem + 1536);
    if (lane == 0) wsum[wid] = loss;
    __syncthreads();
    if (tid == 0){
        float s = 0.f;
        #pragma unroll
        for (int w = 0; w < 16; w++) s += wsum[w];
        g_part[blockIdx.x] = s;
    }
}

// ---------------- kernel 3: deterministic final reduction ----------------
__global__ void reduce_kernel(float* __restrict__ out){
    __shared__ float sm[512];
    const int t = threadIdx.x;
    float v = 0.f;
    for (int i = t; i < NPART; i += 512) v += g_part[i];
    sm[t] = v;
    __syncthreads();
    for (int s = 256; s > 0; s >>= 1){
        if (t < s) sm[t] += sm[t + s];
        __syncthreads();
    }
    if (t == 0) out[0] = sm[0] / (float)NPTS;
}

// ---------------- launch ----------------
extern "C" void kernel_launch(void* const* d_in, const int* in_sizes, int n_in,
                              void* d_out, int out_size){
    const float* x   = (const float*)d_in[0];
    const void*  tgt = d_in[1];
    float* out = (float*)d_out;

    cudaFuncSetAttribute(contrastive_gemm,
                         cudaFuncAttributeMaxDynamicSharedMemorySize, SMEM_BYTES);

    prep_kernel<<<1024, 256>>>(x, tgt);
    contrastive_gemm<<<NPART, 512, SMEM_BYTES>>>();
    reduce_kernel<<<1, 512>>>(out);
}

// round 6
// speedup vs baseline: 1.1881x; 1.0781x over previous
#include <cuda_runtime.h>
#include <cuda_bf16.h>
#include <cstdint>

#define NPTS 8192
#define DIM  512
#define MARGINF 0.3f

#define BM 128
#define BN 128
#define BK 64                    // bf16 elems per K chunk (128 B per row)
#define NCHUNK (DIM/BK)          // 8
#define GB (NPTS/BM)             // 64
#define NPART (GB*(GB+1)/2)      // 2080 upper-triangular tiles

#define STAGES 3
#define STAGE_BYTES 32768        // 16KB A + 16KB B
#define SMEM_BYTES (1024 + STAGES*STAGE_BYTES)

// ---------------- device scratch (no allocations allowed) ----------------
__device__ __nv_bfloat16 g_X[NPTS*DIM];   // 8 MB bf16 copy of inputs
__device__ int   g_lab[NPTS];
__device__ float g_part[NPART];

// ---------------- helpers ----------------
__device__ __forceinline__ uint32_t smem_u32(const void* p){
    uint32_t a;
    asm("{ .reg .u64 t; cvta.to.shared.u64 t, %1; cvt.u32.u64 %0, t; }"
        : "=r"(a) : "l"(p));
    return a;
}
#define SW128(o) ((o) ^ (((o) >> 3) & 0x70))

__device__ __forceinline__ void cp16(uint32_t s, const void* g){
    asm volatile("cp.async.cg.shared.global [%0], [%1], 16;" :: "r"(s), "l"(g));
}
#define CP_COMMIT() asm volatile("cp.async.commit_group;" ::: "memory")
#define CP_WAIT(n)  asm volatile("cp.async.wait_group %0;" :: "n"(n) : "memory")

__device__ __forceinline__ void ldm_x4(uint32_t* r, uint32_t addr){
    asm volatile("ldmatrix.sync.aligned.m8n8.x4.shared.b16 {%0,%1,%2,%3}, [%4];"
                 : "=r"(r[0]), "=r"(r[1]), "=r"(r[2]), "=r"(r[3]) : "r"(addr));
}
__device__ __forceinline__ void mma16816(float* d, const uint32_t* a,
                                         uint32_t b0, uint32_t b1){
    asm volatile(
        "mma.sync.aligned.m16n8k16.row.col.f32.bf16.bf16.f32 "
        "{%0,%1,%2,%3}, {%4,%5,%6,%7}, {%8,%9}, {%0,%1,%2,%3};"
        : "+f"(d[0]), "+f"(d[1]), "+f"(d[2]), "+f"(d[3])
        : "r"(a[0]), "r"(a[1]), "r"(a[2]), "r"(a[3]), "r"(b0), "r"(b1));
}

// ---------------- kernel 1: convert inputs to bf16 + normalize labels ----------------
__global__ void prep_kernel(const float* __restrict__ x, const void* __restrict__ tgt){
    const int idx = blockIdx.x * blockDim.x + threadIdx.x;   // NPTS*DIM/4 threads
    const float4 v = ((const float4*)x)[idx];
    __nv_bfloat162 p0 = __float22bfloat162_rn(make_float2(v.x, v.y));
    __nv_bfloat162 p1 = __float22bfloat162_rn(make_float2(v.z, v.w));
    uint2 st;
    st.x = *(uint32_t*)&p0;
    st.y = *(uint32_t*)&p1;
    ((uint2*)g_X)[idx] = st;

    if (blockIdx.x == 0){
        // detect int64 vs int32 labels: values in [0,128); if int64, all odd words are 0
        const int* w = (const int*)tgt;
        bool is64 = true;
        #pragma unroll 1
        for (int k = 0; k < 64; k++)
            if (w[2*k + 1] != 0) { is64 = false; break; }
        if (is64){
            const long long* t64 = (const long long*)tgt;
            for (int i = threadIdx.x; i < NPTS; i += blockDim.x)
                g_lab[i] = (int)t64[i];
        } else {
            for (int i = threadIdx.x; i < NPTS; i += blockDim.x)
                g_lab[i] = w[i];
        }
    }
}

// ---------------- kernel 2: 128x128 tile, 4 warps (64x64 warp tile), 2 CTA/SM ----------------
__global__ void __launch_bounds__(128, 2) contrastive_gemm(){
    extern __shared__ char smem[];
    const uint32_t sb = smem_u32(smem);
    const int tid = threadIdx.x;
    const int wid = tid >> 5, lane = tid & 31;

    // map blockIdx.x -> upper-triangular (bi, bj), bi <= bj
    int bi = 0, rem = blockIdx.x;
    while (rem >= GB - bi){ rem -= GB - bi; bi++; }
    const int bj = bi + rem;
    const int i0 = bi * BM, j0 = bj * BN;
    const bool diag = (bi == bj);

    // labels into smem: ilab[128] @0, jlab[128] @512
    int* ilab = (int*)smem;
    int* jlab = (int*)(smem + 512);
    ilab[tid] = g_lab[i0 + tid];
    jlab[tid] = g_lab[j0 + tid];

    // cp.async loader: 128 threads, 8 threads x 16B per 128B row, 16 rows/pass
    const int rr = tid >> 3, vv = tid & 7;
    auto load_stage = [&](int c){
        const uint32_t sA = sb + 1024 + (c % STAGES) * STAGE_BYTES;
        const uint32_t sB = sA + 16384;
        const int kc = c * BK;
        #pragma unroll
        for (int p = 0; p < 8; p++){
            const int r = rr + p * 16;
            cp16(sA + SW128(r * 128 + vv * 16),
                 g_X + (size_t)(i0 + r) * DIM + kc + vv * 8);
            cp16(sB + SW128(r * 128 + vv * 16),
                 g_X + (size_t)(j0 + r) * DIM + kc + vv * 8);
        }
    };

    load_stage(0); CP_COMMIT();
    load_stage(1); CP_COMMIT();

    const int wm0 = (wid & 1) * 64;     // 2 warps in M
    const int wn0 = (wid >> 1) * 64;    // 2 warps in N

    float acc[4][8][4];                 // warp tile 64x64 -> 128 floats/thread
    #pragma unroll
    for (int tm = 0; tm < 4; tm++)
        #pragma unroll
        for (int tn = 0; tn < 8; tn++)
            #pragma unroll
            for (int e = 0; e < 4; e++) acc[tm][tn][e] = 0.f;

    const int lrow = lane & 15, lhi = lane >> 4;

    for (int c = 0; c < NCHUNK; c++){
        CP_WAIT(1);
        __syncthreads();                 // single barrier per chunk (3-stage proof)
        if (c + 2 < NCHUNK) load_stage(c + 2);
        CP_COMMIT();                     // empty commits keep group count aligned

        const uint32_t sA = sb + 1024 + (c % STAGES) * STAGE_BYTES;
        const uint32_t sB = sA + 16384;
        #pragma unroll
        for (int ks = 0; ks < 4; ks++){
            const int cb = ks * 32 + lhi * 16;
            uint32_t a[4][4];
            #pragma unroll
            for (int tm = 0; tm < 4; tm++)
                ldm_x4(a[tm], sA + SW128((wm0 + tm * 16 + lrow) * 128 + cb));
            uint32_t b[4][4];
            #pragma unroll
            for (int tp = 0; tp < 4; tp++)
                ldm_x4(b[tp], sB + SW128((wn0 + tp * 16 + lrow) * 128 + cb));
            #pragma unroll
            for (int tm = 0; tm < 4; tm++)
                #pragma unroll
                for (int tp = 0; tp < 4; tp++){
                    mma16816(acc[tm][2*tp],     a[tm], b[tp][0], b[tp][2]);
                    mma16816(acc[tm][2*tp + 1], a[tm], b[tp][1], b[tp][3]);
                }
        }
    }

    // ---------------- fused masked loss on register accumulators ----------------
    const int r0 = lane >> 2, c0 = (lane & 3) * 2;
    float loss = 0.f;
    #pragma unroll
    for (int tm = 0; tm < 4; tm++){
        const int rowA = wm0 + tm * 16 + r0;
        const int liA  = ilab[rowA];
        const int liB  = ilab[rowA + 8];
        #pragma unroll
        for (int tn = 0; tn < 8; tn++){
            const int colb = wn0 + tn * 8 + c0;
            const int lj0 = jlab[colb], lj1 = jlab[colb + 1];
            #pragma unroll
            for (int e = 0; e < 4; e++){
                const float v = acc[tm][tn][e];
                const int row = (e >> 1) ? rowA + 8 : rowA;
                const int li  = (e >> 1) ? liB : liA;
                const int lj  = (e & 1) ? lj1 : lj0;
                float w = 2.f;
                if (diag){
                    const int gi = row, gj = colb + (e & 1);
                    w = (gi < gj) ? 2.f : ((gi == gj) ? 1.f : 0.f);
                }
                float l;
                if (li == lj) l = (v < 1.f) ? (1.f - v) : 0.f;
                else          l = (v > MARGINF) ? v : 0.f;
                loss += w * l;
            }
        }
    }

    // block reduction -> per-tile partial
    #pragma unroll
    for (int o = 16; o; o >>= 1) loss += __shfl_xor_sync(0xffffffffu, loss, o);
    float* wsum = (float*)(smem + 768);
    if (lane == 0) wsum[wid] = loss;
    __syncthreads();
    if (tid == 0){
        float s = 0.f;
        #pragma unroll
        for (int w = 0; w < 4; w++) s += wsum[w];
        g_part[blockIdx.x] = s;
    }
}

// ---------------- kernel 3: deterministic final reduction ----------------
__global__ void reduce_kernel(float* __restrict__ out){
    __shared__ float sm[512];
    const int t = threadIdx.x;
    float v = 0.f;
    for (int i = t; i < NPART; i += 512) v += g_part[i];
    sm[t] = v;
    __syncthreads();
    for (int s = 256; s > 0; s >>= 1){
        if (t < s) sm[t] += sm[t + s];
        __syncthreads();
    }
    if (t == 0) out[0] = sm[0] / (float)NPTS;
}

// ---------------- launch ----------------
extern "C" void kernel_launch(void* const* d_in, const int* in_sizes, int n_in,
                              void* d_out, int out_size){
    const float* x   = (const float*)d_in[0];
    const void*  tgt = d_in[1];
    float* out = (float*)d_out;

    cudaFuncSetAttribute(contrastive_gemm,
                         cudaFuncAttributeMaxDynamicSharedMemorySize, SMEM_BYTES);

    prep_kernel<<<NPTS*DIM/1024, 256>>>(x, tgt);
    contrastive_gemm<<<NPART, 128, SMEM_BYTES>>>();
    reduce_kernel<<<1, 512>>>(out);
}